// round 7
// baseline (speedup 1.0000x reference)
#include <cuda_runtime.h>
#include <cuda_bf16.h>
#include <cstdint>

// ---------------- problem constants ----------------
#define BATCH   256
#define NH      12
#define HD      64
#define DIM     768          // NH*HD
#define WIN     14
#define NTOK    196          // WIN*WIN
#define MTOT    (BATCH*NTOK) // 50176
#define REL     27           // 2*WIN-1

// ---------------- scratch (device globals; no allocation allowed) -------
__device__ float g_q[BATCH*NH*NTOK*HD];   // [b][h][n][d], pre-scaled by 1/8
__device__ float g_k[BATCH*NH*NTOK*HD];   // [b][h][n][d]
__device__ float g_v[BATCH*NH*NTOK*HD];   // TRANSPOSED: [b][h][d][n]

// bf16 hi/lo split operands for the GEMMs
__device__ __nv_bfloat16 g_xH[MTOT*DIM],  g_xL[MTOT*DIM];    // x split
__device__ __nv_bfloat16 g_wqH[3*DIM*DIM], g_wqL[3*DIM*DIM]; // qkv_w split
__device__ __nv_bfloat16 g_wpH[DIM*DIM],  g_wpL[DIM*DIM];    // proj_w split
__device__ __nv_bfloat16 g_aoH[MTOT*DIM], g_aoL[MTOT*DIM];   // attn out split

// =========================================================================
// helpers
// =========================================================================
__device__ __forceinline__ void mma_bf16(float c[4],
                                         uint32_t a0, uint32_t a1, uint32_t a2, uint32_t a3,
                                         uint32_t b0, uint32_t b1)
{
    asm volatile(
        "mma.sync.aligned.m16n8k16.row.col.f32.bf16.bf16.f32 "
        "{%0,%1,%2,%3}, {%4,%5,%6,%7}, {%8,%9}, {%0,%1,%2,%3};"
        : "+f"(c[0]), "+f"(c[1]), "+f"(c[2]), "+f"(c[3])
        : "r"(a0), "r"(a1), "r"(a2), "r"(a3), "r"(b0), "r"(b1));
}

// pack (x0,x1) -> bf16x2 hi (x0 in low half) and bf16x2 residual lo
__device__ __forceinline__ void pack_hl(float x0, float x1, uint32_t& hi, uint32_t& lo)
{
    uint32_t h;
    asm("cvt.rn.bf16x2.f32 %0, %1, %2;" : "=r"(h) : "f"(x1), "f"(x0));
    float h0 = __uint_as_float(h << 16);
    float h1 = __uint_as_float(h & 0xFFFF0000u);
    float l0 = x0 - h0;
    float l1 = x1 - h1;
    uint32_t l;
    asm("cvt.rn.bf16x2.f32 %0, %1, %2;" : "=r"(l) : "f"(l1), "f"(l0));
    hi = h; lo = l;
}

__device__ __forceinline__ void cp16(uint32_t dst, const void* src)
{
    asm volatile("cp.async.cg.shared.global [%0], [%1], 16;" :: "r"(dst), "l"(src));
}

// =========================================================================
// one-shot fp32 -> bf16 hi/lo split kernels (WHICH selects destination)
// =========================================================================
template<int WHICH>
__global__ __launch_bounds__(256) void split_kernel(const float* __restrict__ src, int n2)
{
    const int i = blockIdx.x * 256 + threadIdx.x;
    if (i >= n2) return;
    float2 v = ((const float2*)src)[i];
    uint32_t h, l;
    pack_hl(v.x, v.y, h, l);
    uint32_t* H;
    uint32_t* L;
    if (WHICH == 0)      { H = (uint32_t*)g_xH;  L = (uint32_t*)g_xL;  }
    else if (WHICH == 1) { H = (uint32_t*)g_wqH; L = (uint32_t*)g_wqL; }
    else                 { H = (uint32_t*)g_wpH; L = (uint32_t*)g_wpL; }
    H[i] = h;
    L[i] = l;
}

// =========================================================================
// bf16 mma.sync GEMM, operands pre-split in global. cp.async double buffer,
// 2 CTAs/SM. CTA tile 128x128, BK=32, 256 threads = 8 warps (2M x 4N).
// Smem per stage: AH/AL/BH/BL bf16 128x32, row stride 40 bf16 (80B).
// MODE 0: A=g_x*, B=g_wq*, QKV scatter epilogue.  MODE 1: A=g_ao*, B=g_wp*.
// =========================================================================
#define KSTR   40                       // bf16 smem row stride
#define TILE_B (128*KSTR*2)             // 10240 bytes per tile
#define STAGE_B (4*TILE_B)              // 40960 bytes per stage
#define GEMM_SMEM (2*STAGE_B)           // 81920 bytes

template<int MODE>
__global__ __launch_bounds__(256, 2) void gemm_mma(const float* __restrict__ bias,
                                                   float* __restrict__ out)
{
    extern __shared__ __nv_bfloat16 S[];   // [2 stages][4 tiles][128][KSTR]

    const int tid = threadIdx.x;
    const int m0  = blockIdx.y * 128;
    const int n0  = blockIdx.x * 128;

    const int w    = tid >> 5;
    const int lane = tid & 31;
    const int g    = lane >> 2;
    const int t    = lane & 3;
    const int wm   = (w >> 2) * 64;
    const int wn   = (w & 3) * 32;

    // ---- cp.async loader mapping: 4 groups of 64 threads, 2 rows each ----
    const int tile = tid >> 6;           // 0=AH 1=AL 2=BH 3=BL
    const int r0l  = (tid & 63) * 2;
    const __nv_bfloat16* gbase;
    int rowbase;
    if (tile == 0)      { gbase = (MODE ? g_aoH : g_xH);  rowbase = m0; }
    else if (tile == 1) { gbase = (MODE ? g_aoL : g_xL);  rowbase = m0; }
    else if (tile == 2) { gbase = (MODE ? g_wpH : g_wqH); rowbase = n0; }
    else                { gbase = (MODE ? g_wpL : g_wqL); rowbase = n0; }
    const __nv_bfloat16* gp0 = gbase + (size_t)(rowbase + r0l) * 768;
    const __nv_bfloat16* gp1 = gp0 + 768;
    const uint32_t sb = (uint32_t)__cvta_generic_to_shared(S)
                      + tile * TILE_B + r0l * (KSTR * 2);

    float acc[4][4][4];
#pragma unroll
    for (int i = 0; i < 4; i++)
#pragma unroll
        for (int j = 0; j < 4; j++)
#pragma unroll
            for (int r = 0; r < 4; r++) acc[i][j][r] = 0.f;

    // prologue: stage 0
    {
        const uint32_t d = sb;
#pragma unroll
        for (int c = 0; c < 4; c++) {
            cp16(d + c * 16,            gp0 + c * 8);
            cp16(d + KSTR * 2 + c * 16, gp1 + c * 8);
        }
        asm volatile("cp.async.commit_group;");
    }

    int stage = 0;
    for (int i = 0; i < 24; i++) {
        if (i + 1 < 24) {
            const int k0 = (i + 1) * 32;
            const uint32_t d = sb + (stage ^ 1) * STAGE_B;
#pragma unroll
            for (int c = 0; c < 4; c++) {
                cp16(d + c * 16,            gp0 + k0 + c * 8);
                cp16(d + KSTR * 2 + c * 16, gp1 + k0 + c * 8);
            }
            asm volatile("cp.async.commit_group;");
            asm volatile("cp.async.wait_group 1;");
        } else {
            asm volatile("cp.async.wait_group 0;");
        }
        __syncthreads();

        const __nv_bfloat16* AsH = S + stage * (STAGE_B / 2);
        const __nv_bfloat16* AsL = AsH + (TILE_B / 2);
        const __nv_bfloat16* BsH = AsL + (TILE_B / 2);
        const __nv_bfloat16* BsL = BsH + (TILE_B / 2);

#pragma unroll
        for (int ks = 0; ks < 2; ks++) {
            const int kb = ks * 16 + 2 * t;
            uint32_t ah[4][4], al[4][4], bh[4][2], bl[4][2];
#pragma unroll
            for (int mt = 0; mt < 4; mt++) {
                const int ro = (wm + mt * 16 + g) * KSTR + kb;
                ah[mt][0] = *(const uint32_t*)&AsH[ro];
                ah[mt][1] = *(const uint32_t*)&AsH[ro + 8 * KSTR];
                ah[mt][2] = *(const uint32_t*)&AsH[ro + 8];
                ah[mt][3] = *(const uint32_t*)&AsH[ro + 8 * KSTR + 8];
                al[mt][0] = *(const uint32_t*)&AsL[ro];
                al[mt][1] = *(const uint32_t*)&AsL[ro + 8 * KSTR];
                al[mt][2] = *(const uint32_t*)&AsL[ro + 8];
                al[mt][3] = *(const uint32_t*)&AsL[ro + 8 * KSTR + 8];
            }
#pragma unroll
            for (int nt = 0; nt < 4; nt++) {
                const int ro = (wn + nt * 8 + g) * KSTR + kb;
                bh[nt][0] = *(const uint32_t*)&BsH[ro];
                bh[nt][1] = *(const uint32_t*)&BsH[ro + 8];
                bl[nt][0] = *(const uint32_t*)&BsL[ro];
                bl[nt][1] = *(const uint32_t*)&BsL[ro + 8];
            }
#pragma unroll
            for (int mt = 0; mt < 4; mt++)
#pragma unroll
                for (int nt = 0; nt < 4; nt++) {
                    mma_bf16(acc[mt][nt], ah[mt][0], ah[mt][1], ah[mt][2], ah[mt][3],
                             bl[nt][0], bl[nt][1]);
                    mma_bf16(acc[mt][nt], al[mt][0], al[mt][1], al[mt][2], al[mt][3],
                             bh[nt][0], bh[nt][1]);
                    mma_bf16(acc[mt][nt], ah[mt][0], ah[mt][1], ah[mt][2], ah[mt][3],
                             bh[nt][0], bh[nt][1]);
                }
        }
        __syncthreads();
        stage ^= 1;
    }

    // ----- epilogue -----
#pragma unroll
    for (int mt = 0; mt < 4; mt++) {
#pragma unroll
        for (int half = 0; half < 2; half++) {
            const int m = m0 + wm + mt * 16 + g + half * 8;
            if (MODE == 0) {
                const int b = m / NTOK;
                const int n = m - b * NTOK;
#pragma unroll
                for (int nt = 0; nt < 4; nt++) {
#pragma unroll
                    for (int e = 0; e < 2; e++) {
                        const int col = n0 + wn + nt * 8 + 2 * t + e;
                        float v = acc[mt][nt][half * 2 + e] + bias[col];
                        const int which = col / DIM;          // 0=q,1=k,2=v
                        const int rem   = col - which * DIM;
                        const int h     = rem >> 6;
                        const int dd    = rem & 63;
                        if (which == 0)
                            g_q[((b * NH + h) * NTOK + n) * HD + dd] = v * 0.125f;
                        else if (which == 1)
                            g_k[((b * NH + h) * NTOK + n) * HD + dd] = v;
                        else // V transposed: [b][h][d][n]
                            g_v[((b * NH + h) * HD + dd) * NTOK + n] = v;
                    }
                }
            } else {
#pragma unroll
                for (int nt = 0; nt < 4; nt++) {
                    const int col = n0 + wn + nt * 8 + 2 * t;
                    float2 v;
                    v.x = acc[mt][nt][half * 2 + 0] + bias[col];
                    v.y = acc[mt][nt][half * 2 + 1] + bias[col + 1];
                    *(float2*)&out[m * DIM + col] = v;
                }
            }
        }
    }
}

// =========================================================================
// Tensor-core flash attention, one CTA per (b,h). 416 threads = 13 warps,
// one m16 tile per warp. Output written as bf16 hi/lo (for proj GEMM).
// =========================================================================
#define KS_STR  72                                // K/Vt smem row stride (bf16)
#define SRH_OFF 0
#define SRW_OFF (SRH_OFF + REL*HD*4)
#define SBH_OFF (SRW_OFF + REL*HD*4)
#define SBW_OFF (SBH_OFF + 208*14*4)
#define SKH_OFF (SBW_OFF + 208*14*4)
#define SKL_OFF (SKH_OFF + 64*KS_STR*2)
#define SVH_OFF (SKL_OFF + 64*KS_STR*2)
#define SVL_OFF (SVH_OFF + 64*KS_STR*2)
#define ATT_SMEM (SVL_OFF + 64*KS_STR*2)          // 73984 bytes

#define ATHR 416

__global__ __launch_bounds__(ATHR, 1) void attn_mma(const float* __restrict__ relh,
                                                    const float* __restrict__ relw)
{
    extern __shared__ char smc[];
    float* RH = (float*)(smc + SRH_OFF);
    float* RW = (float*)(smc + SRW_OFF);
    float* BH = (float*)(smc + SBH_OFF);
    float* BW = (float*)(smc + SBW_OFF);
    __nv_bfloat16* KH = (__nv_bfloat16*)(smc + SKH_OFF);
    __nv_bfloat16* KL = (__nv_bfloat16*)(smc + SKL_OFF);
    __nv_bfloat16* VH = (__nv_bfloat16*)(smc + SVH_OFF);
    __nv_bfloat16* VL = (__nv_bfloat16*)(smc + SVL_OFF);

    const int bh  = blockIdx.x;
    const int tid = threadIdx.x;
    const int w    = tid >> 5;
    const int lane = tid & 31;
    const int g    = lane >> 2;
    const int t    = lane & 3;

    const float* qg = g_q + bh * NTOK * HD;
    const float* kg = g_k + bh * NTOK * HD;
    const float* vg = g_v + bh * HD * NTOK;    // transposed [d][n]

    for (int idx = tid; idx < REL * HD / 4; idx += ATHR) {
        ((float4*)RH)[idx] = ((const float4*)relh)[idx];
        ((float4*)RW)[idx] = ((const float4*)relw)[idx];
    }
    __syncthreads();

    // decomposed rel-pos bias (scalar, once)
    if (tid < NTOK) {
        float4 q4[16];
        const float4* qr = (const float4*)(qg + tid * HD);
#pragma unroll
        for (int i = 0; i < 16; i++) q4[i] = qr[i];
        const int qh = tid / WIN, qw = tid - qh * WIN;
#pragma unroll 1
        for (int kk = 0; kk < WIN; kk++) {
            const float4* rh4 = (const float4*)(RH + (qh - kk + WIN - 1) * HD);
            const float4* rw4 = (const float4*)(RW + (qw - kk + WIN - 1) * HD);
            float sh = 0.f, sw = 0.f;
#pragma unroll
            for (int i = 0; i < 16; i++) {
                float4 a = q4[i], r = rh4[i], wv = rw4[i];
                sh += a.x * r.x + a.y * r.y + a.z * r.z + a.w * r.w;
                sw += a.x * wv.x + a.y * wv.y + a.z * wv.z + a.w * wv.w;
            }
            BH[tid * WIN + kk] = sh;
            BW[tid * WIN + kk] = sw;
        }
    } else if (tid < 208) {
#pragma unroll
        for (int kk = 0; kk < WIN; kk++) {
            BH[tid * WIN + kk] = 0.f;
            BW[tid * WIN + kk] = 0.f;
        }
    }

    // Q fragments from global (once; pad rows clamped -> unused)
    const int r0 = w * 16 + g;
    const int r1 = r0 + 8;
    const int rq0 = (r0 < NTOK) ? r0 : NTOK - 1;
    const int rq1 = (r1 < NTOK) ? r1 : NTOK - 1;
    uint32_t qfh[4][4], qfl[4][4];
#pragma unroll
    for (int kt = 0; kt < 4; kt++) {
        const int kc = kt * 16 + 2 * t;
        float2 v0 = *(const float2*)(qg + rq0 * HD + kc);
        float2 v1 = *(const float2*)(qg + rq1 * HD + kc);
        float2 v2 = *(const float2*)(qg + rq0 * HD + kc + 8);
        float2 v3 = *(const float2*)(qg + rq1 * HD + kc + 8);
        pack_hl(v0.x, v0.y, qfh[kt][0], qfl[kt][0]);
        pack_hl(v1.x, v1.y, qfh[kt][1], qfl[kt][1]);
        pack_hl(v2.x, v2.y, qfh[kt][2], qfl[kt][2]);
        pack_hl(v3.x, v3.y, qfh[kt][3], qfl[kt][3]);
    }

    float oacc[8][4];
#pragma unroll
    for (int j = 0; j < 8; j++)
#pragma unroll
        for (int r = 0; r < 4; r++) oacc[j][r] = 0.f;
    float lsum0 = 0.f, lsum1 = 0.f;

#pragma unroll 1
    for (int chunk = 0; chunk < 4; chunk++) {
        const int j0 = chunk * 64;
        __syncthreads();

        for (int idx = tid; idx < 64 * 64; idx += ATHR) {
            const int r = idx >> 6, c = idx & 63;
            float kvv = (j0 + r < NTOK) ? kg[(j0 + r) * HD + c] : 0.f;
            __nv_bfloat16 hb = __float2bfloat16(kvv);
            KH[r * KS_STR + c] = hb;
            KL[r * KS_STR + c] = __float2bfloat16(kvv - __bfloat162float(hb));
            float vvv = (j0 + c < NTOK) ? vg[r * NTOK + j0 + c] : 0.f;
            __nv_bfloat16 vb = __float2bfloat16(vvv);
            VH[r * KS_STR + c] = vb;
            VL[r * KS_STR + c] = __float2bfloat16(vvv - __bfloat162float(vb));
        }
        __syncthreads();

        float sacc[8][4];
#pragma unroll
        for (int j = 0; j < 8; j++)
#pragma unroll
            for (int r = 0; r < 4; r++) sacc[j][r] = 0.f;

#pragma unroll
        for (int kt = 0; kt < 4; kt++) {
            const int kc = kt * 16 + 2 * t;
#pragma unroll
            for (int nt = 0; nt < 8; nt++) {
                const int krow = (nt * 8 + g) * KS_STR + kc;
                uint32_t kh0 = *(const uint32_t*)&KH[krow];
                uint32_t kh1 = *(const uint32_t*)&KH[krow + 8];
                uint32_t kl0 = *(const uint32_t*)&KL[krow];
                uint32_t kl1 = *(const uint32_t*)&KL[krow + 8];
                mma_bf16(sacc[nt], qfh[kt][0], qfh[kt][1], qfh[kt][2], qfh[kt][3], kl0, kl1);
                mma_bf16(sacc[nt], qfl[kt][0], qfl[kt][1], qfl[kt][2], qfl[kt][3], kh0, kh1);
                mma_bf16(sacc[nt], qfh[kt][0], qfh[kt][1], qfh[kt][2], qfh[kt][3], kh0, kh1);
            }
        }

#pragma unroll
        for (int nt = 0; nt < 8; nt++) {
#pragma unroll
            for (int e = 0; e < 2; e++) {
                const int c = j0 + nt * 8 + 2 * t + e;
                float p0 = 0.f, p1 = 0.f;
                if (c < NTOK) {
                    const int kh = c / WIN;
                    const int kw = c - kh * WIN;
                    p0 = __expf(sacc[nt][e]     + BH[r0 * WIN + kh] + BW[r0 * WIN + kw]);
                    p1 = __expf(sacc[nt][2 + e] + BH[r1 * WIN + kh] + BW[r1 * WIN + kw]);
                }
                sacc[nt][e]     = p0;
                sacc[nt][2 + e] = p1;
                lsum0 += p0;
                lsum1 += p1;
            }
        }

#pragma unroll
        for (int kt = 0; kt < 4; kt++) {
            uint32_t ph[4], pl[4];
            pack_hl(sacc[2*kt][0],   sacc[2*kt][1],   ph[0], pl[0]);
            pack_hl(sacc[2*kt][2],   sacc[2*kt][3],   ph[1], pl[1]);
            pack_hl(sacc[2*kt+1][0], sacc[2*kt+1][1], ph[2], pl[2]);
            pack_hl(sacc[2*kt+1][2], sacc[2*kt+1][3], ph[3], pl[3]);
            const int kc = kt * 16 + 2 * t;
#pragma unroll
            for (int nt = 0; nt < 8; nt++) {
                const int vrow = (nt * 8 + g) * KS_STR + kc;
                uint32_t vh0 = *(const uint32_t*)&VH[vrow];
                uint32_t vh1 = *(const uint32_t*)&VH[vrow + 8];
                uint32_t vl0 = *(const uint32_t*)&VL[vrow];
                uint32_t vl1 = *(const uint32_t*)&VL[vrow + 8];
                mma_bf16(oacc[nt], ph[0], ph[1], ph[2], ph[3], vl0, vl1);
                mma_bf16(oacc[nt], pl[0], pl[1], pl[2], pl[3], vh0, vh1);
                mma_bf16(oacc[nt], ph[0], ph[1], ph[2], ph[3], vh0, vh1);
            }
        }
    }

    // finalize: reduce l across t-quad, normalize, store bf16 hi/lo
    lsum0 += __shfl_xor_sync(0xffffffff, lsum0, 1);
    lsum0 += __shfl_xor_sync(0xffffffff, lsum0, 2);
    lsum1 += __shfl_xor_sync(0xffffffff, lsum1, 1);
    lsum1 += __shfl_xor_sync(0xffffffff, lsum1, 2);

    const int b = bh / NH, h = bh - (bh / NH) * NH;
    const float inv0 = 1.f / lsum0;
    const float inv1 = 1.f / lsum1;
    if (r0 < NTOK) {
        const int off = (b * NTOK + r0) * DIM + h * HD;
#pragma unroll
        for (int nt = 0; nt < 8; nt++) {
            uint32_t hp, lp;
            pack_hl(oacc[nt][0] * inv0, oacc[nt][1] * inv0, hp, lp);
            *(uint32_t*)&g_aoH[off + nt * 8 + 2 * t] = hp;
            *(uint32_t*)&g_aoL[off + nt * 8 + 2 * t] = lp;
        }
    }
    if (r1 < NTOK) {
        const int off = (b * NTOK + r1) * DIM + h * HD;
#pragma unroll
        for (int nt = 0; nt < 8; nt++) {
            uint32_t hp, lp;
            pack_hl(oacc[nt][2] * inv1, oacc[nt][3] * inv1, hp, lp);
            *(uint32_t*)&g_aoH[off + nt * 8 + 2 * t] = hp;
            *(uint32_t*)&g_aoL[off + nt * 8 + 2 * t] = lp;
        }
    }
}

// =========================================================================
extern "C" void kernel_launch(void* const* d_in, const int* in_sizes, int n_in,
                              void* d_out, int out_size)
{
    const float* x      = (const float*)d_in[0];
    const float* qkv_w  = (const float*)d_in[1];
    const float* qkv_b  = (const float*)d_in[2];
    const float* relh   = (const float*)d_in[3];
    const float* relw   = (const float*)d_in[4];
    const float* proj_w = (const float*)d_in[5];
    const float* proj_b = (const float*)d_in[6];
    float* out = (float*)d_out;

    cudaFuncSetAttribute(attn_mma,
                         cudaFuncAttributeMaxDynamicSharedMemorySize, ATT_SMEM);
    cudaFuncSetAttribute(gemm_mma<0>,
                         cudaFuncAttributeMaxDynamicSharedMemorySize, GEMM_SMEM);
    cudaFuncSetAttribute(gemm_mma<1>,
                         cudaFuncAttributeMaxDynamicSharedMemorySize, GEMM_SMEM);

    // 0) one-shot bf16 hi/lo splits
    {
        const int n2x = MTOT * DIM / 2;
        split_kernel<0><<<(n2x + 255) / 256, 256>>>(x, n2x);
        const int n2q = 3 * DIM * DIM / 2;
        split_kernel<1><<<(n2q + 255) / 256, 256>>>(qkv_w, n2q);
        const int n2p = DIM * DIM / 2;
        split_kernel<2><<<(n2p + 255) / 256, 256>>>(proj_w, n2p);
    }

    // 1) QKV GEMM -> g_q/g_k scatter, g_v transposed
    gemm_mma<0><<<dim3(2304 / 128, MTOT / 128), 256, GEMM_SMEM>>>(qkv_b, nullptr);

    // 2) tensor-core flash attention per (b, head) -> g_aoH/g_aoL
    attn_mma<<<BATCH * NH, ATHR, ATT_SMEM>>>(relh, relw);

    // 3) proj GEMM -> d_out
    gemm_mma<1><<<dim3(DIM / 128, MTOT / 128), 256, GEMM_SMEM>>>(proj_b, out);
}

// round 8
// speedup vs baseline: 1.0622x; 1.0622x over previous
#include <cuda_runtime.h>
#include <cuda_bf16.h>
#include <cstdint>

// ---------------- problem constants ----------------
#define BATCH   256
#define NH      12
#define HD      64
#define DIM     768          // NH*HD
#define WIN     14
#define NTOK    196          // WIN*WIN
#define NPAD    256          // padded token count for K/V tiles
#define MTOT    (BATCH*NTOK) // 50176
#define REL     27           // 2*WIN-1

// ---------------- scratch (device globals; no allocation allowed) -------
__device__ float g_q[BATCH*NH*NTOK*HD];                      // fp32 [b][h][n][d], q*0.125
__device__ __nv_bfloat16 g_kH[BATCH*NH*NPAD*HD], g_kL[BATCH*NH*NPAD*HD]; // [b][h][n][d]
__device__ __nv_bfloat16 g_vH[BATCH*NH*HD*NPAD], g_vL[BATCH*NH*HD*NPAD]; // [b][h][d][n]
__device__ __nv_bfloat16 g_xH[MTOT*DIM],  g_xL[MTOT*DIM];    // x split
__device__ __nv_bfloat16 g_wqH[3*DIM*DIM], g_wqL[3*DIM*DIM]; // qkv_w split
__device__ __nv_bfloat16 g_wpH[DIM*DIM],  g_wpL[DIM*DIM];    // proj_w split
__device__ __nv_bfloat16 g_aoH[MTOT*DIM], g_aoL[MTOT*DIM];   // attn out split

// =========================================================================
// helpers
// =========================================================================
__device__ __forceinline__ void mma_bf16(float c[4],
                                         uint32_t a0, uint32_t a1, uint32_t a2, uint32_t a3,
                                         uint32_t b0, uint32_t b1)
{
    asm volatile(
        "mma.sync.aligned.m16n8k16.row.col.f32.bf16.bf16.f32 "
        "{%0,%1,%2,%3}, {%4,%5,%6,%7}, {%8,%9}, {%0,%1,%2,%3};"
        : "+f"(c[0]), "+f"(c[1]), "+f"(c[2]), "+f"(c[3])
        : "r"(a0), "r"(a1), "r"(a2), "r"(a3), "r"(b0), "r"(b1));
}

__device__ __forceinline__ void pack_hl(float x0, float x1, uint32_t& hi, uint32_t& lo)
{
    uint32_t h;
    asm("cvt.rn.bf16x2.f32 %0, %1, %2;" : "=r"(h) : "f"(x1), "f"(x0));
    float h0 = __uint_as_float(h << 16);
    float h1 = __uint_as_float(h & 0xFFFF0000u);
    float l0 = x0 - h0;
    float l1 = x1 - h1;
    uint32_t l;
    asm("cvt.rn.bf16x2.f32 %0, %1, %2;" : "=r"(l) : "f"(l1), "f"(l0));
    hi = h; lo = l;
}

__device__ __forceinline__ void cp16(uint32_t dst, const void* src)
{
    asm volatile("cp.async.cg.shared.global [%0], [%1], 16;" :: "r"(dst), "l"(src));
}
#define CP_COMMIT() asm volatile("cp.async.commit_group;")
#define CP_WAIT(n)  asm volatile("cp.async.wait_group %0;" :: "n"(n))

// =========================================================================
// one-shot fp32 -> bf16 hi/lo split kernels
// =========================================================================
template<int WHICH>
__global__ __launch_bounds__(256) void split_kernel(const float* __restrict__ src, int n2)
{
    const int i = blockIdx.x * 256 + threadIdx.x;
    if (i >= n2) return;
    float2 v = ((const float2*)src)[i];
    uint32_t h, l;
    pack_hl(v.x, v.y, h, l);
    uint32_t* H;
    uint32_t* L;
    if (WHICH == 0)      { H = (uint32_t*)g_xH;  L = (uint32_t*)g_xL;  }
    else if (WHICH == 1) { H = (uint32_t*)g_wqH; L = (uint32_t*)g_wqL; }
    else                 { H = (uint32_t*)g_wpH; L = (uint32_t*)g_wpL; }
    H[i] = h;
    L[i] = l;
}

// =========================================================================
// bf16 mma GEMM, pre-split operands, 256x128 CTA tile, BK=32, 3-stage
// cp.async. 256 threads = 8 warps (4M x 2N), warp tile 64x64.
// MODE 0: A=x, B=qkv_w -> q/k/v scatter.  MODE 1: A=ao, B=proj_w -> out.
// =========================================================================
#define KSTR 40                                 // bf16 smem row stride
#define G_AH 0
#define G_AL (256*KSTR)                         // 10240 (bf16 units)
#define G_BH (2*256*KSTR)                       // 20480
#define G_BL (2*256*KSTR + 128*KSTR)            // 25600
#define G_STAGE (2*256*KSTR + 2*128*KSTR)       // 30720 bf16 = 61440 B
#define GEMM_SMEM (3*G_STAGE*2)                 // 184320 B

template<int MODE>
__global__ __launch_bounds__(256) void gemm_mma(const float* __restrict__ bias,
                                                float* __restrict__ out)
{
    extern __shared__ __nv_bfloat16 S[];

    const int tid = threadIdx.x;
    const int m0  = blockIdx.y * 256;
    const int n0  = blockIdx.x * 128;

    const int w    = tid >> 5;
    const int lane = tid & 31;
    const int g    = lane >> 2;
    const int t    = lane & 3;
    const int wm   = (w >> 1) * 64;   // 0..192
    const int wn   = (w & 1) * 64;    // 0/64

    const __nv_bfloat16* gAH = MODE ? g_aoH : g_xH;
    const __nv_bfloat16* gAL = MODE ? g_aoL : g_xL;
    const __nv_bfloat16* gBH = MODE ? g_wpH : g_wqH;
    const __nv_bfloat16* gBL = MODE ? g_wpL : g_wqL;

    // loader: thread -> A row tid (AH+AL), B row tid&127 (BH if tid<128 else BL)
    const __nv_bfloat16* srcAH = gAH + (size_t)(m0 + tid) * 768;
    const __nv_bfloat16* srcAL = gAL + (size_t)(m0 + tid) * 768;
    const int rb = tid & 127;
    const __nv_bfloat16* srcB  = (tid < 128 ? gBH : gBL) + (size_t)(n0 + rb) * 768;

    const uint32_t sbase = (uint32_t)__cvta_generic_to_shared(S);
    const uint32_t dA_H = sbase + tid * (KSTR * 2);
    const uint32_t dA_L = sbase + G_AL * 2 + tid * (KSTR * 2);
    const uint32_t dB   = sbase + (tid < 128 ? G_BH : G_BL) * 2 + rb * (KSTR * 2);

#define ISSUE_STAGE(s, k0)                                         \
    {                                                              \
        const uint32_t so = (uint32_t)(s) * (G_STAGE * 2);         \
        _Pragma("unroll")                                          \
        for (int c = 0; c < 4; c++) {                              \
            cp16(dA_H + so + c * 16, srcAH + (k0) + c * 8);        \
            cp16(dA_L + so + c * 16, srcAL + (k0) + c * 8);        \
            cp16(dB   + so + c * 16, srcB  + (k0) + c * 8);        \
        }                                                          \
        CP_COMMIT();                                               \
    }

    float acc[4][8][4];
#pragma unroll
    for (int i = 0; i < 4; i++)
#pragma unroll
        for (int j = 0; j < 8; j++)
#pragma unroll
            for (int r = 0; r < 4; r++) acc[i][j][r] = 0.f;

    ISSUE_STAGE(0, 0);
    ISSUE_STAGE(1, 32);

    for (int i = 0; i < 24; i++) {
        CP_WAIT(1);
        __syncthreads();
        if (i + 2 < 24) {
            const int s = (i + 2) % 3;
            const int k0 = (i + 2) * 32;
            ISSUE_STAGE(s, k0);
        }

        const __nv_bfloat16* AsH = S + (i % 3) * G_STAGE;
        const __nv_bfloat16* AsL = AsH + G_AL;
        const __nv_bfloat16* BsH = AsH + G_BH;
        const __nv_bfloat16* BsL = AsH + G_BL;

#pragma unroll
        for (int ks = 0; ks < 2; ks++) {
            const int kb = ks * 16 + 2 * t;
            uint32_t ah[4][4], al[4][4], bh[8][2], bl[8][2];
#pragma unroll
            for (int mt = 0; mt < 4; mt++) {
                const int ro = (wm + mt * 16 + g) * KSTR + kb;
                ah[mt][0] = *(const uint32_t*)&AsH[ro];
                ah[mt][1] = *(const uint32_t*)&AsH[ro + 8 * KSTR];
                ah[mt][2] = *(const uint32_t*)&AsH[ro + 8];
                ah[mt][3] = *(const uint32_t*)&AsH[ro + 8 * KSTR + 8];
                al[mt][0] = *(const uint32_t*)&AsL[ro];
                al[mt][1] = *(const uint32_t*)&AsL[ro + 8 * KSTR];
                al[mt][2] = *(const uint32_t*)&AsL[ro + 8];
                al[mt][3] = *(const uint32_t*)&AsL[ro + 8 * KSTR + 8];
            }
#pragma unroll
            for (int nt = 0; nt < 8; nt++) {
                const int ro = (wn + nt * 8 + g) * KSTR + kb;
                bh[nt][0] = *(const uint32_t*)&BsH[ro];
                bh[nt][1] = *(const uint32_t*)&BsH[ro + 8];
                bl[nt][0] = *(const uint32_t*)&BsL[ro];
                bl[nt][1] = *(const uint32_t*)&BsL[ro + 8];
            }
#pragma unroll
            for (int mt = 0; mt < 4; mt++)
#pragma unroll
                for (int nt = 0; nt < 8; nt++) {
                    mma_bf16(acc[mt][nt], ah[mt][0], ah[mt][1], ah[mt][2], ah[mt][3],
                             bl[nt][0], bl[nt][1]);
                    mma_bf16(acc[mt][nt], al[mt][0], al[mt][1], al[mt][2], al[mt][3],
                             bh[nt][0], bh[nt][1]);
                    mma_bf16(acc[mt][nt], ah[mt][0], ah[mt][1], ah[mt][2], ah[mt][3],
                             bh[nt][0], bh[nt][1]);
                }
        }
    }

    // ----- epilogue -----
#pragma unroll
    for (int mt = 0; mt < 4; mt++) {
#pragma unroll
        for (int half = 0; half < 2; half++) {
            const int m = m0 + wm + mt * 16 + g + half * 8;
            if (MODE == 0) {
                const int b = m / NTOK;
                const int n = m - b * NTOK;
#pragma unroll
                for (int nt = 0; nt < 8; nt++) {
                    const int col0 = n0 + nt * 8 + 2 * t + (w & 1) * 64;
                    float v0 = acc[mt][nt][half * 2 + 0] + bias[col0];
                    float v1 = acc[mt][nt][half * 2 + 1] + bias[col0 + 1];
                    const int which = col0 / DIM;
                    const int rem   = col0 - which * DIM;
                    const int h     = rem >> 6;
                    const int dd    = rem & 63;
                    const int bhI   = b * NH + h;
                    if (which == 0) {
                        float2 q2 = make_float2(v0 * 0.125f, v1 * 0.125f);
                        *(float2*)&g_q[((size_t)bhI * NTOK + n) * HD + dd] = q2;
                    } else if (which == 1) {
                        uint32_t hp, lp;
                        pack_hl(v0, v1, hp, lp);
                        const size_t idx = ((size_t)bhI * NPAD + n) * HD + dd;
                        *(uint32_t*)&g_kH[idx] = hp;
                        *(uint32_t*)&g_kL[idx] = lp;
                    } else {
                        const size_t i0 = ((size_t)bhI * HD + dd) * NPAD + n;
                        __nv_bfloat16 h0 = __float2bfloat16(v0);
                        __nv_bfloat16 h1 = __float2bfloat16(v1);
                        g_vH[i0]        = h0;
                        g_vH[i0 + NPAD] = h1;
                        g_vL[i0]        = __float2bfloat16(v0 - __bfloat162float(h0));
                        g_vL[i0 + NPAD] = __float2bfloat16(v1 - __bfloat162float(h1));
                    }
                }
            } else {
#pragma unroll
                for (int nt = 0; nt < 8; nt++) {
                    const int col = n0 + (w & 1) * 64 + nt * 8 + 2 * t;
                    float2 v;
                    v.x = acc[mt][nt][half * 2 + 0] + bias[col];
                    v.y = acc[mt][nt][half * 2 + 1] + bias[col + 1];
                    *(float2*)&out[(size_t)m * DIM + col] = v;
                }
            }
        }
    }
}

// =========================================================================
// Tensor-core flash attention, one CTA per (b,h). 416 threads = 13 warps,
// one m16 tile per warp. K/V pre-split bf16 in global; chunks staged via
// cp.async, double buffered. Output -> g_aoH/g_aoL.
// =========================================================================
#define KS_STR  72                                // bf16 row stride
#define KV_TILE (64*KS_STR*2)                     // 9216 B per tile
#define KV_STAGE (4*KV_TILE)                      // 36864 B
#define SRH_OFF 0
#define SRW_OFF (SRH_OFF + REL*HD*4)
#define SBH_OFF (SRW_OFF + REL*HD*4)
#define SBW_OFF (SBH_OFF + 208*14*4)
#define SKV_OFF (SBW_OFF + 208*14*4)
#define ATT_SMEM (SKV_OFF + 2*KV_STAGE)           // 110848 B

#define ATHR 416

__global__ __launch_bounds__(ATHR, 1) void attn_mma(const float* __restrict__ relh,
                                                    const float* __restrict__ relw)
{
    extern __shared__ char smc[];
    float* RH = (float*)(smc + SRH_OFF);
    float* RW = (float*)(smc + SRW_OFF);
    float* BH = (float*)(smc + SBH_OFF);
    float* BW = (float*)(smc + SBW_OFF);

    const int bh  = blockIdx.x;
    const int tid = threadIdx.x;
    const int w    = tid >> 5;
    const int lane = tid & 31;
    const int g    = lane >> 2;
    const int t    = lane & 3;

    const float* qg = g_q + (size_t)bh * NTOK * HD;
    const uint32_t kvbase = (uint32_t)__cvta_generic_to_shared(smc + SKV_OFF);

    // prefetch chunk 0 (overlaps bias prologue)
#define PREFETCH_CHUNK(j0, s)                                              \
    {                                                                      \
        for (int idx = tid; idx < 2048; idx += ATHR) {                     \
            const int tile = idx >> 9;                                     \
            const int r    = (idx >> 3) & 63;                              \
            const int c8   = idx & 7;                                      \
            const __nv_bfloat16* src;                                      \
            if (tile == 0)      src = g_kH + ((size_t)bh * NPAD + (j0) + r) * HD + c8 * 8; \
            else if (tile == 1) src = g_kL + ((size_t)bh * NPAD + (j0) + r) * HD + c8 * 8; \
            else if (tile == 2) src = g_vH + ((size_t)bh * HD + r) * NPAD + (j0) + c8 * 8; \
            else                src = g_vL + ((size_t)bh * HD + r) * NPAD + (j0) + c8 * 8; \
            cp16(kvbase + (s) * KV_STAGE + tile * KV_TILE + r * (KS_STR*2) + c8 * 16, src); \
        }                                                                  \
        CP_COMMIT();                                                       \
    }

    PREFETCH_CHUNK(0, 0);

    for (int idx = tid; idx < REL * HD / 4; idx += ATHR) {
        ((float4*)RH)[idx] = ((const float4*)relh)[idx];
        ((float4*)RW)[idx] = ((const float4*)relw)[idx];
    }
    __syncthreads();

    // decomposed rel-pos bias (scalar, once)
    if (tid < NTOK) {
        float4 q4[16];
        const float4* qr = (const float4*)(qg + tid * HD);
#pragma unroll
        for (int i = 0; i < 16; i++) q4[i] = qr[i];
        const int qh = tid / WIN, qw = tid - qh * WIN;
#pragma unroll 1
        for (int kk = 0; kk < WIN; kk++) {
            const float4* rh4 = (const float4*)(RH + (qh - kk + WIN - 1) * HD);
            const float4* rw4 = (const float4*)(RW + (qw - kk + WIN - 1) * HD);
            float sh = 0.f, sw = 0.f;
#pragma unroll
            for (int i = 0; i < 16; i++) {
                float4 a = q4[i], r = rh4[i], wv = rw4[i];
                sh += a.x * r.x + a.y * r.y + a.z * r.z + a.w * r.w;
                sw += a.x * wv.x + a.y * wv.y + a.z * wv.z + a.w * wv.w;
            }
            BH[tid * WIN + kk] = sh;
            BW[tid * WIN + kk] = sw;
        }
    } else if (tid < 208) {
#pragma unroll
        for (int kk = 0; kk < WIN; kk++) {
            BH[tid * WIN + kk] = 0.f;
            BW[tid * WIN + kk] = 0.f;
        }
    }

    // Q fragments (once; pad rows clamped)
    const int r0 = w * 16 + g;
    const int r1 = r0 + 8;
    const int rq0 = (r0 < NTOK) ? r0 : NTOK - 1;
    const int rq1 = (r1 < NTOK) ? r1 : NTOK - 1;
    uint32_t qfh[4][4], qfl[4][4];
#pragma unroll
    for (int kt = 0; kt < 4; kt++) {
        const int kc = kt * 16 + 2 * t;
        float2 v0 = *(const float2*)(qg + rq0 * HD + kc);
        float2 v1 = *(const float2*)(qg + rq1 * HD + kc);
        float2 v2 = *(const float2*)(qg + rq0 * HD + kc + 8);
        float2 v3 = *(const float2*)(qg + rq1 * HD + kc + 8);
        pack_hl(v0.x, v0.y, qfh[kt][0], qfl[kt][0]);
        pack_hl(v1.x, v1.y, qfh[kt][1], qfl[kt][1]);
        pack_hl(v2.x, v2.y, qfh[kt][2], qfl[kt][2]);
        pack_hl(v3.x, v3.y, qfh[kt][3], qfl[kt][3]);
    }

    float oacc[8][4];
#pragma unroll
    for (int j = 0; j < 8; j++)
#pragma unroll
        for (int r = 0; r < 4; r++) oacc[j][r] = 0.f;
    float lsum0 = 0.f, lsum1 = 0.f;

#pragma unroll 1
    for (int chunk = 0; chunk < 4; chunk++) {
        const int j0 = chunk * 64;
        const int s  = chunk & 1;
        CP_WAIT(0);
        __syncthreads();
        if (chunk < 3) PREFETCH_CHUNK(j0 + 64, s ^ 1);

        const __nv_bfloat16* KH = (const __nv_bfloat16*)(smc + SKV_OFF + s * KV_STAGE);
        const __nv_bfloat16* KL = KH + 64 * KS_STR;
        const __nv_bfloat16* VH = KH + 2 * 64 * KS_STR;
        const __nv_bfloat16* VL = KH + 3 * 64 * KS_STR;

        float sacc[8][4];
#pragma unroll
        for (int j = 0; j < 8; j++)
#pragma unroll
            for (int r = 0; r < 4; r++) sacc[j][r] = 0.f;

#pragma unroll
        for (int kt = 0; kt < 4; kt++) {
            const int kc = kt * 16 + 2 * t;
#pragma unroll
            for (int nt = 0; nt < 8; nt++) {
                const int krow = (nt * 8 + g) * KS_STR + kc;
                uint32_t kh0 = *(const uint32_t*)&KH[krow];
                uint32_t kh1 = *(const uint32_t*)&KH[krow + 8];
                uint32_t kl0 = *(const uint32_t*)&KL[krow];
                uint32_t kl1 = *(const uint32_t*)&KL[krow + 8];
                mma_bf16(sacc[nt], qfh[kt][0], qfh[kt][1], qfh[kt][2], qfh[kt][3], kl0, kl1);
                mma_bf16(sacc[nt], qfl[kt][0], qfl[kt][1], qfl[kt][2], qfl[kt][3], kh0, kh1);
                mma_bf16(sacc[nt], qfh[kt][0], qfh[kt][1], qfh[kt][2], qfh[kt][3], kh0, kh1);
            }
        }

#pragma unroll
        for (int nt = 0; nt < 8; nt++) {
#pragma unroll
            for (int e = 0; e < 2; e++) {
                const int c = j0 + nt * 8 + 2 * t + e;
                float p0 = 0.f, p1 = 0.f;
                if (c < NTOK) {
                    const int kh = c / WIN;
                    const int kw = c - kh * WIN;
                    p0 = __expf(sacc[nt][e]     + BH[r0 * WIN + kh] + BW[r0 * WIN + kw]);
                    p1 = __expf(sacc[nt][2 + e] + BH[r1 * WIN + kh] + BW[r1 * WIN + kw]);
                }
                sacc[nt][e]     = p0;
                sacc[nt][2 + e] = p1;
                lsum0 += p0;
                lsum1 += p1;
            }
        }

#pragma unroll
        for (int kt = 0; kt < 4; kt++) {
            uint32_t ph[4], pl[4];
            pack_hl(sacc[2*kt][0],   sacc[2*kt][1],   ph[0], pl[0]);
            pack_hl(sacc[2*kt][2],   sacc[2*kt][3],   ph[1], pl[1]);
            pack_hl(sacc[2*kt+1][0], sacc[2*kt+1][1], ph[2], pl[2]);
            pack_hl(sacc[2*kt+1][2], sacc[2*kt+1][3], ph[3], pl[3]);
            const int kc = kt * 16 + 2 * t;
#pragma unroll
            for (int nt = 0; nt < 8; nt++) {
                const int vrow = (nt * 8 + g) * KS_STR + kc;
                uint32_t vh0 = *(const uint32_t*)&VH[vrow];
                uint32_t vh1 = *(const uint32_t*)&VH[vrow + 8];
                uint32_t vl0 = *(const uint32_t*)&VL[vrow];
                uint32_t vl1 = *(const uint32_t*)&VL[vrow + 8];
                mma_bf16(oacc[nt], ph[0], ph[1], ph[2], ph[3], vl0, vl1);
                mma_bf16(oacc[nt], pl[0], pl[1], pl[2], pl[3], vh0, vh1);
                mma_bf16(oacc[nt], ph[0], ph[1], ph[2], ph[3], vh0, vh1);
            }
        }
    }

    // finalize
    lsum0 += __shfl_xor_sync(0xffffffff, lsum0, 1);
    lsum0 += __shfl_xor_sync(0xffffffff, lsum0, 2);
    lsum1 += __shfl_xor_sync(0xffffffff, lsum1, 1);
    lsum1 += __shfl_xor_sync(0xffffffff, lsum1, 2);

    const int b = bh / NH, h = bh - (bh / NH) * NH;
    const float inv0 = 1.f / lsum0;
    const float inv1 = 1.f / lsum1;
    if (r0 < NTOK) {
        const size_t off = ((size_t)b * NTOK + r0) * DIM + h * HD;
#pragma unroll
        for (int nt = 0; nt < 8; nt++) {
            uint32_t hp, lp;
            pack_hl(oacc[nt][0] * inv0, oacc[nt][1] * inv0, hp, lp);
            *(uint32_t*)&g_aoH[off + nt * 8 + 2 * t] = hp;
            *(uint32_t*)&g_aoL[off + nt * 8 + 2 * t] = lp;
        }
    }
    if (r1 < NTOK) {
        const size_t off = ((size_t)b * NTOK + r1) * DIM + h * HD;
#pragma unroll
        for (int nt = 0; nt < 8; nt++) {
            uint32_t hp, lp;
            pack_hl(oacc[nt][2] * inv1, oacc[nt][3] * inv1, hp, lp);
            *(uint32_t*)&g_aoH[off + nt * 8 + 2 * t] = hp;
            *(uint32_t*)&g_aoL[off + nt * 8 + 2 * t] = lp;
        }
    }
}

// =========================================================================
extern "C" void kernel_launch(void* const* d_in, const int* in_sizes, int n_in,
                              void* d_out, int out_size)
{
    const float* x      = (const float*)d_in[0];
    const float* qkv_w  = (const float*)d_in[1];
    const float* qkv_b  = (const float*)d_in[2];
    const float* relh   = (const float*)d_in[3];
    const float* relw   = (const float*)d_in[4];
    const float* proj_w = (const float*)d_in[5];
    const float* proj_b = (const float*)d_in[6];
    float* out = (float*)d_out;

    cudaFuncSetAttribute(attn_mma,
                         cudaFuncAttributeMaxDynamicSharedMemorySize, ATT_SMEM);
    cudaFuncSetAttribute(gemm_mma<0>,
                         cudaFuncAttributeMaxDynamicSharedMemorySize, GEMM_SMEM);
    cudaFuncSetAttribute(gemm_mma<1>,
                         cudaFuncAttributeMaxDynamicSharedMemorySize, GEMM_SMEM);

    // 0) one-shot bf16 hi/lo splits
    {
        const int n2x = MTOT * DIM / 2;
        split_kernel<0><<<(n2x + 255) / 256, 256>>>(x, n2x);
        const int n2q = 3 * DIM * DIM / 2;
        split_kernel<1><<<(n2q + 255) / 256, 256>>>(qkv_w, n2q);
        const int n2p = DIM * DIM / 2;
        split_kernel<2><<<(n2p + 255) / 256, 256>>>(proj_w, n2p);
    }

    // 1) QKV GEMM -> g_q (fp32), g_k hi/lo, g_v hi/lo transposed
    gemm_mma<0><<<dim3(2304 / 128, MTOT / 256), 256, GEMM_SMEM>>>(qkv_b, nullptr);

    // 2) tensor-core flash attention per (b, head) -> g_aoH/g_aoL
    attn_mma<<<BATCH * NH, ATHR, ATT_SMEM>>>(relh, relw);

    // 3) proj GEMM -> d_out
    gemm_mma<1><<<dim3(DIM / 128, MTOT / 256), 256, GEMM_SMEM>>>(proj_b, out);
}

// round 9
// speedup vs baseline: 1.1409x; 1.0741x over previous
#include <cuda_runtime.h>
#include <cuda_bf16.h>
#include <cstdint>

// ---------------- problem constants ----------------
#define BATCH   256
#define NH      12
#define HD      64
#define DIM     768          // NH*HD
#define WIN     14
#define NTOK    196          // WIN*WIN
#define NPAD    256          // padded token count for K/V tiles
#define MTOT    (BATCH*NTOK) // 50176
#define REL     27           // 2*WIN-1

// ---------------- scratch (device globals; no allocation allowed) -------
__device__ float g_q[BATCH*NH*NTOK*HD];                      // fp32, q*0.125
__device__ __nv_bfloat16 g_kH[BATCH*NH*NPAD*HD], g_kL[BATCH*NH*NPAD*HD]; // [b][h][n][d]
__device__ __nv_bfloat16 g_vH[BATCH*NH*HD*NPAD], g_vL[BATCH*NH*HD*NPAD]; // [b][h][d][n]
__device__ __nv_bfloat16 g_xH[MTOT*DIM],  g_xL[MTOT*DIM];    // x split
__device__ __nv_bfloat16 g_wqH[3*DIM*DIM], g_wqL[3*DIM*DIM]; // qkv_w split
__device__ __nv_bfloat16 g_wpH[DIM*DIM],  g_wpL[DIM*DIM];    // proj_w split
__device__ __nv_bfloat16 g_aoH[MTOT*DIM], g_aoL[MTOT*DIM];   // attn out split

// =========================================================================
// helpers
// =========================================================================
__device__ __forceinline__ void mma_bf16(float c[4],
                                         uint32_t a0, uint32_t a1, uint32_t a2, uint32_t a3,
                                         uint32_t b0, uint32_t b1)
{
    asm volatile(
        "mma.sync.aligned.m16n8k16.row.col.f32.bf16.bf16.f32 "
        "{%0,%1,%2,%3}, {%4,%5,%6,%7}, {%8,%9}, {%0,%1,%2,%3};"
        : "+f"(c[0]), "+f"(c[1]), "+f"(c[2]), "+f"(c[3])
        : "r"(a0), "r"(a1), "r"(a2), "r"(a3), "r"(b0), "r"(b1));
}

__device__ __forceinline__ void pack_hl(float x0, float x1, uint32_t& hi, uint32_t& lo)
{
    uint32_t h;
    asm("cvt.rn.bf16x2.f32 %0, %1, %2;" : "=r"(h) : "f"(x1), "f"(x0));
    float h0 = __uint_as_float(h << 16);
    float h1 = __uint_as_float(h & 0xFFFF0000u);
    float l0 = x0 - h0;
    float l1 = x1 - h1;
    uint32_t l;
    asm("cvt.rn.bf16x2.f32 %0, %1, %2;" : "=r"(l) : "f"(l1), "f"(l0));
    hi = h; lo = l;
}

__device__ __forceinline__ void cp16(uint32_t dst, const void* src)
{
    asm volatile("cp.async.cg.shared.global [%0], [%1], 16;" :: "r"(dst), "l"(src));
}
#define CP_COMMIT() asm volatile("cp.async.commit_group;")
#define CP_WAIT(n)  asm volatile("cp.async.wait_group %0;" :: "n"(n))

// =========================================================================
// one-shot fp32 -> bf16 hi/lo split kernels
// =========================================================================
template<int WHICH>
__global__ __launch_bounds__(256) void split_kernel(const float* __restrict__ src, int n2)
{
    const int i = blockIdx.x * 256 + threadIdx.x;
    if (i >= n2) return;
    float2 v = ((const float2*)src)[i];
    uint32_t h, l;
    pack_hl(v.x, v.y, h, l);
    uint32_t* H;
    uint32_t* L;
    if (WHICH == 0)      { H = (uint32_t*)g_xH;  L = (uint32_t*)g_xL;  }
    else if (WHICH == 1) { H = (uint32_t*)g_wqH; L = (uint32_t*)g_wqL; }
    else                 { H = (uint32_t*)g_wpH; L = (uint32_t*)g_wpL; }
    H[i] = h;
    L[i] = l;
}

// =========================================================================
// bf16 mma GEMM: round-4 reg-prefetch structure + pre-split operands.
// CTA tile 128x128, BK=32, 256 threads = 8 warps (2M x 4N), warp 64x32.
// Smem: AsH/AsL/BsH/BsL bf16 [128][40].
// MODE 0: A=x, B=qkv_w -> q fp32 / k,v bf16 hi-lo scatter.  MODE 1: proj.
// =========================================================================
#define KSTR 40                       // bf16 smem row stride

template<int MODE>
__global__ __launch_bounds__(256) void gemm_mma(const float* __restrict__ bias,
                                                float* __restrict__ out)
{
    __shared__ __nv_bfloat16 AsH[128 * KSTR];
    __shared__ __nv_bfloat16 AsL[128 * KSTR];
    __shared__ __nv_bfloat16 BsH[128 * KSTR];
    __shared__ __nv_bfloat16 BsL[128 * KSTR];

    const int tid = threadIdx.x;
    const int m0  = blockIdx.y * 128;
    const int n0  = blockIdx.x * 128;

    const int w    = tid >> 5;
    const int lane = tid & 31;
    const int g    = lane >> 2;
    const int t    = lane & 3;
    const int wm   = (w >> 2) * 64;
    const int wn   = (w & 3) * 32;

    // loader: 4 threads/row x 16B; rows lr and lr+64 per array
    const int lr = tid >> 2;          // 0..63
    const int lc = (tid & 3) * 8;     // bf16 col 0,8,16,24

    const __nv_bfloat16* gAH = (MODE ? g_aoH : g_xH) + (size_t)(m0 + lr) * 768 + lc;
    const __nv_bfloat16* gAL = (MODE ? g_aoL : g_xL) + (size_t)(m0 + lr) * 768 + lc;
    const __nv_bfloat16* gBH = (MODE ? g_wpH : g_wqH) + (size_t)(n0 + lr) * 768 + lc;
    const __nv_bfloat16* gBL = (MODE ? g_wpL : g_wqL) + (size_t)(n0 + lr) * 768 + lc;
    const size_t rstep = (size_t)64 * 768;

    float acc[4][4][4];
#pragma unroll
    for (int i = 0; i < 4; i++)
#pragma unroll
        for (int j = 0; j < 4; j++)
#pragma unroll
            for (int r = 0; r < 4; r++) acc[i][j][r] = 0.f;

    uint4 pah[2], pal[2], pbh[2], pbl[2];
    pah[0] = *(const uint4*)(gAH);          pah[1] = *(const uint4*)(gAH + rstep);
    pal[0] = *(const uint4*)(gAL);          pal[1] = *(const uint4*)(gAL + rstep);
    pbh[0] = *(const uint4*)(gBH);          pbh[1] = *(const uint4*)(gBH + rstep);
    pbl[0] = *(const uint4*)(gBL);          pbl[1] = *(const uint4*)(gBL + rstep);

    for (int k0 = 0; k0 < 768; k0 += 32) {
        // store prefetched tile
#pragma unroll
        for (int i = 0; i < 2; i++) {
            const int ro = (lr + i * 64) * KSTR + lc;
            *(uint4*)&AsH[ro] = pah[i];
            *(uint4*)&AsL[ro] = pal[i];
            *(uint4*)&BsH[ro] = pbh[i];
            *(uint4*)&BsL[ro] = pbl[i];
        }
        __syncthreads();

        // prefetch next
        if (k0 + 32 < 768) {
            const int k1 = k0 + 32;
            pah[0] = *(const uint4*)(gAH + k1);          pah[1] = *(const uint4*)(gAH + k1 + rstep);
            pal[0] = *(const uint4*)(gAL + k1);          pal[1] = *(const uint4*)(gAL + k1 + rstep);
            pbh[0] = *(const uint4*)(gBH + k1);          pbh[1] = *(const uint4*)(gBH + k1 + rstep);
            pbl[0] = *(const uint4*)(gBL + k1);          pbl[1] = *(const uint4*)(gBL + k1 + rstep);
        }

#pragma unroll
        for (int ks = 0; ks < 2; ks++) {
            const int kb = ks * 16 + 2 * t;
            uint32_t ah[4][4], al[4][4], bh[4][2], bl[4][2];
#pragma unroll
            for (int mt = 0; mt < 4; mt++) {
                const int ro = (wm + mt * 16 + g) * KSTR + kb;
                ah[mt][0] = *(const uint32_t*)&AsH[ro];
                ah[mt][1] = *(const uint32_t*)&AsH[ro + 8 * KSTR];
                ah[mt][2] = *(const uint32_t*)&AsH[ro + 8];
                ah[mt][3] = *(const uint32_t*)&AsH[ro + 8 * KSTR + 8];
                al[mt][0] = *(const uint32_t*)&AsL[ro];
                al[mt][1] = *(const uint32_t*)&AsL[ro + 8 * KSTR];
                al[mt][2] = *(const uint32_t*)&AsL[ro + 8];
                al[mt][3] = *(const uint32_t*)&AsL[ro + 8 * KSTR + 8];
            }
#pragma unroll
            for (int nt = 0; nt < 4; nt++) {
                const int ro = (wn + nt * 8 + g) * KSTR + kb;
                bh[nt][0] = *(const uint32_t*)&BsH[ro];
                bh[nt][1] = *(const uint32_t*)&BsH[ro + 8];
                bl[nt][0] = *(const uint32_t*)&BsL[ro];
                bl[nt][1] = *(const uint32_t*)&BsL[ro + 8];
            }
#pragma unroll
            for (int mt = 0; mt < 4; mt++)
#pragma unroll
                for (int nt = 0; nt < 4; nt++) {
                    mma_bf16(acc[mt][nt], ah[mt][0], ah[mt][1], ah[mt][2], ah[mt][3],
                             bl[nt][0], bl[nt][1]);
                    mma_bf16(acc[mt][nt], al[mt][0], al[mt][1], al[mt][2], al[mt][3],
                             bh[nt][0], bh[nt][1]);
                    mma_bf16(acc[mt][nt], ah[mt][0], ah[mt][1], ah[mt][2], ah[mt][3],
                             bh[nt][0], bh[nt][1]);
                }
        }
        __syncthreads();
    }

    // ----- epilogue -----
#pragma unroll
    for (int mt = 0; mt < 4; mt++) {
#pragma unroll
        for (int half = 0; half < 2; half++) {
            const int m = m0 + wm + mt * 16 + g + half * 8;
            if (MODE == 0) {
                const int b = m / NTOK;
                const int n = m - b * NTOK;
#pragma unroll
                for (int nt = 0; nt < 4; nt++) {
                    const int col0 = n0 + wn + nt * 8 + 2 * t;
                    float v0 = acc[mt][nt][half * 2 + 0] + bias[col0];
                    float v1 = acc[mt][nt][half * 2 + 1] + bias[col0 + 1];
                    const int which = col0 / DIM;
                    const int rem   = col0 - which * DIM;
                    const int h     = rem >> 6;
                    const int dd    = rem & 63;
                    const int bhI   = b * NH + h;
                    if (which == 0) {
                        float2 q2 = make_float2(v0 * 0.125f, v1 * 0.125f);
                        *(float2*)&g_q[((size_t)bhI * NTOK + n) * HD + dd] = q2;
                    } else if (which == 1) {
                        uint32_t hp, lp;
                        pack_hl(v0, v1, hp, lp);
                        const size_t idx = ((size_t)bhI * NPAD + n) * HD + dd;
                        *(uint32_t*)&g_kH[idx] = hp;
                        *(uint32_t*)&g_kL[idx] = lp;
                    } else {
                        const size_t i0 = ((size_t)bhI * HD + dd) * NPAD + n;
                        __nv_bfloat16 h0 = __float2bfloat16(v0);
                        __nv_bfloat16 h1 = __float2bfloat16(v1);
                        g_vH[i0]        = h0;
                        g_vH[i0 + NPAD] = h1;
                        g_vL[i0]        = __float2bfloat16(v0 - __bfloat162float(h0));
                        g_vL[i0 + NPAD] = __float2bfloat16(v1 - __bfloat162float(h1));
                    }
                }
            } else {
#pragma unroll
                for (int nt = 0; nt < 4; nt++) {
                    const int col = n0 + wn + nt * 8 + 2 * t;
                    float2 v;
                    v.x = acc[mt][nt][half * 2 + 0] + bias[col];
                    v.y = acc[mt][nt][half * 2 + 1] + bias[col + 1];
                    *(float2*)&out[(size_t)m * DIM + col] = v;
                }
            }
        }
    }
}

// =========================================================================
// Tensor-core flash attention (unchanged from round 8).
// =========================================================================
#define KS_STR  72
#define KV_TILE (64*KS_STR*2)
#define KV_STAGE (4*KV_TILE)
#define SRH_OFF 0
#define SRW_OFF (SRH_OFF + REL*HD*4)
#define SBH_OFF (SRW_OFF + REL*HD*4)
#define SBW_OFF (SBH_OFF + 208*14*4)
#define SKV_OFF (SBW_OFF + 208*14*4)
#define ATT_SMEM (SKV_OFF + 2*KV_STAGE)           // 110848 B

#define ATHR 416

__global__ __launch_bounds__(ATHR, 1) void attn_mma(const float* __restrict__ relh,
                                                    const float* __restrict__ relw)
{
    extern __shared__ char smc[];
    float* RH = (float*)(smc + SRH_OFF);
    float* RW = (float*)(smc + SRW_OFF);
    float* BH = (float*)(smc + SBH_OFF);
    float* BW = (float*)(smc + SBW_OFF);

    const int bh  = blockIdx.x;
    const int tid = threadIdx.x;
    const int w    = tid >> 5;
    const int lane = tid & 31;
    const int g    = lane >> 2;
    const int t    = lane & 3;

    const float* qg = g_q + (size_t)bh * NTOK * HD;
    const uint32_t kvbase = (uint32_t)__cvta_generic_to_shared(smc + SKV_OFF);

#define PREFETCH_CHUNK(j0, s)                                              \
    {                                                                      \
        for (int idx = tid; idx < 2048; idx += ATHR) {                     \
            const int tile = idx >> 9;                                     \
            const int r    = (idx >> 3) & 63;                              \
            const int c8   = idx & 7;                                      \
            const __nv_bfloat16* src;                                      \
            if (tile == 0)      src = g_kH + ((size_t)bh * NPAD + (j0) + r) * HD + c8 * 8; \
            else if (tile == 1) src = g_kL + ((size_t)bh * NPAD + (j0) + r) * HD + c8 * 8; \
            else if (tile == 2) src = g_vH + ((size_t)bh * HD + r) * NPAD + (j0) + c8 * 8; \
            else                src = g_vL + ((size_t)bh * HD + r) * NPAD + (j0) + c8 * 8; \
            cp16(kvbase + (s) * KV_STAGE + tile * KV_TILE + r * (KS_STR*2) + c8 * 16, src); \
        }                                                                  \
        CP_COMMIT();                                                       \
    }

    PREFETCH_CHUNK(0, 0);

    for (int idx = tid; idx < REL * HD / 4; idx += ATHR) {
        ((float4*)RH)[idx] = ((const float4*)relh)[idx];
        ((float4*)RW)[idx] = ((const float4*)relw)[idx];
    }
    __syncthreads();

    if (tid < NTOK) {
        float4 q4[16];
        const float4* qr = (const float4*)(qg + tid * HD);
#pragma unroll
        for (int i = 0; i < 16; i++) q4[i] = qr[i];
        const int qh = tid / WIN, qw = tid - qh * WIN;
#pragma unroll 1
        for (int kk = 0; kk < WIN; kk++) {
            const float4* rh4 = (const float4*)(RH + (qh - kk + WIN - 1) * HD);
            const float4* rw4 = (const float4*)(RW + (qw - kk + WIN - 1) * HD);
            float sh = 0.f, sw = 0.f;
#pragma unroll
            for (int i = 0; i < 16; i++) {
                float4 a = q4[i], r = rh4[i], wv = rw4[i];
                sh += a.x * r.x + a.y * r.y + a.z * r.z + a.w * r.w;
                sw += a.x * wv.x + a.y * wv.y + a.z * wv.z + a.w * wv.w;
            }
            BH[tid * WIN + kk] = sh;
            BW[tid * WIN + kk] = sw;
        }
    } else if (tid < 208) {
#pragma unroll
        for (int kk = 0; kk < WIN; kk++) {
            BH[tid * WIN + kk] = 0.f;
            BW[tid * WIN + kk] = 0.f;
        }
    }

    const int r0 = w * 16 + g;
    const int r1 = r0 + 8;
    const int rq0 = (r0 < NTOK) ? r0 : NTOK - 1;
    const int rq1 = (r1 < NTOK) ? r1 : NTOK - 1;
    uint32_t qfh[4][4], qfl[4][4];
#pragma unroll
    for (int kt = 0; kt < 4; kt++) {
        const int kc = kt * 16 + 2 * t;
        float2 v0 = *(const float2*)(qg + rq0 * HD + kc);
        float2 v1 = *(const float2*)(qg + rq1 * HD + kc);
        float2 v2 = *(const float2*)(qg + rq0 * HD + kc + 8);
        float2 v3 = *(const float2*)(qg + rq1 * HD + kc + 8);
        pack_hl(v0.x, v0.y, qfh[kt][0], qfl[kt][0]);
        pack_hl(v1.x, v1.y, qfh[kt][1], qfl[kt][1]);
        pack_hl(v2.x, v2.y, qfh[kt][2], qfl[kt][2]);
        pack_hl(v3.x, v3.y, qfh[kt][3], qfl[kt][3]);
    }

    float oacc[8][4];
#pragma unroll
    for (int j = 0; j < 8; j++)
#pragma unroll
        for (int r = 0; r < 4; r++) oacc[j][r] = 0.f;
    float lsum0 = 0.f, lsum1 = 0.f;

#pragma unroll 1
    for (int chunk = 0; chunk < 4; chunk++) {
        const int j0 = chunk * 64;
        const int s  = chunk & 1;
        CP_WAIT(0);
        __syncthreads();
        if (chunk < 3) PREFETCH_CHUNK(j0 + 64, s ^ 1);

        const __nv_bfloat16* KH = (const __nv_bfloat16*)(smc + SKV_OFF + s * KV_STAGE);
        const __nv_bfloat16* KL = KH + 64 * KS_STR;
        const __nv_bfloat16* VH = KH + 2 * 64 * KS_STR;
        const __nv_bfloat16* VL = KH + 3 * 64 * KS_STR;

        float sacc[8][4];
#pragma unroll
        for (int j = 0; j < 8; j++)
#pragma unroll
            for (int r = 0; r < 4; r++) sacc[j][r] = 0.f;

#pragma unroll
        for (int kt = 0; kt < 4; kt++) {
            const int kc = kt * 16 + 2 * t;
#pragma unroll
            for (int nt = 0; nt < 8; nt++) {
                const int krow = (nt * 8 + g) * KS_STR + kc;
                uint32_t kh0 = *(const uint32_t*)&KH[krow];
                uint32_t kh1 = *(const uint32_t*)&KH[krow + 8];
                uint32_t kl0 = *(const uint32_t*)&KL[krow];
                uint32_t kl1 = *(const uint32_t*)&KL[krow + 8];
                mma_bf16(sacc[nt], qfh[kt][0], qfh[kt][1], qfh[kt][2], qfh[kt][3], kl0, kl1);
                mma_bf16(sacc[nt], qfl[kt][0], qfl[kt][1], qfl[kt][2], qfl[kt][3], kh0, kh1);
                mma_bf16(sacc[nt], qfh[kt][0], qfh[kt][1], qfh[kt][2], qfh[kt][3], kh0, kh1);
            }
        }

#pragma unroll
        for (int nt = 0; nt < 8; nt++) {
#pragma unroll
            for (int e = 0; e < 2; e++) {
                const int c = j0 + nt * 8 + 2 * t + e;
                float p0 = 0.f, p1 = 0.f;
                if (c < NTOK) {
                    const int kh = c / WIN;
                    const int kw = c - kh * WIN;
                    p0 = __expf(sacc[nt][e]     + BH[r0 * WIN + kh] + BW[r0 * WIN + kw]);
                    p1 = __expf(sacc[nt][2 + e] + BH[r1 * WIN + kh] + BW[r1 * WIN + kw]);
                }
                sacc[nt][e]     = p0;
                sacc[nt][2 + e] = p1;
                lsum0 += p0;
                lsum1 += p1;
            }
        }

#pragma unroll
        for (int kt = 0; kt < 4; kt++) {
            uint32_t ph[4], pl[4];
            pack_hl(sacc[2*kt][0],   sacc[2*kt][1],   ph[0], pl[0]);
            pack_hl(sacc[2*kt][2],   sacc[2*kt][3],   ph[1], pl[1]);
            pack_hl(sacc[2*kt+1][0], sacc[2*kt+1][1], ph[2], pl[2]);
            pack_hl(sacc[2*kt+1][2], sacc[2*kt+1][3], ph[3], pl[3]);
            const int kc = kt * 16 + 2 * t;
#pragma unroll
            for (int nt = 0; nt < 8; nt++) {
                const int vrow = (nt * 8 + g) * KS_STR + kc;
                uint32_t vh0 = *(const uint32_t*)&VH[vrow];
                uint32_t vh1 = *(const uint32_t*)&VH[vrow + 8];
                uint32_t vl0 = *(const uint32_t*)&VL[vrow];
                uint32_t vl1 = *(const uint32_t*)&VL[vrow + 8];
                mma_bf16(oacc[nt], ph[0], ph[1], ph[2], ph[3], vl0, vl1);
                mma_bf16(oacc[nt], pl[0], pl[1], pl[2], pl[3], vh0, vh1);
                mma_bf16(oacc[nt], ph[0], ph[1], ph[2], ph[3], vh0, vh1);
            }
        }
    }

    lsum0 += __shfl_xor_sync(0xffffffff, lsum0, 1);
    lsum0 += __shfl_xor_sync(0xffffffff, lsum0, 2);
    lsum1 += __shfl_xor_sync(0xffffffff, lsum1, 1);
    lsum1 += __shfl_xor_sync(0xffffffff, lsum1, 2);

    const int b = bh / NH, h = bh - (bh / NH) * NH;
    const float inv0 = 1.f / lsum0;
    const float inv1 = 1.f / lsum1;
    if (r0 < NTOK) {
        const size_t off = ((size_t)b * NTOK + r0) * DIM + h * HD;
#pragma unroll
        for (int nt = 0; nt < 8; nt++) {
            uint32_t hp, lp;
            pack_hl(oacc[nt][0] * inv0, oacc[nt][1] * inv0, hp, lp);
            *(uint32_t*)&g_aoH[off + nt * 8 + 2 * t] = hp;
            *(uint32_t*)&g_aoL[off + nt * 8 + 2 * t] = lp;
        }
    }
    if (r1 < NTOK) {
        const size_t off = ((size_t)b * NTOK + r1) * DIM + h * HD;
#pragma unroll
        for (int nt = 0; nt < 8; nt++) {
            uint32_t hp, lp;
            pack_hl(oacc[nt][2] * inv1, oacc[nt][3] * inv1, hp, lp);
            *(uint32_t*)&g_aoH[off + nt * 8 + 2 * t] = hp;
            *(uint32_t*)&g_aoL[off + nt * 8 + 2 * t] = lp;
        }
    }
}

// =========================================================================
extern "C" void kernel_launch(void* const* d_in, const int* in_sizes, int n_in,
                              void* d_out, int out_size)
{
    const float* x      = (const float*)d_in[0];
    const float* qkv_w  = (const float*)d_in[1];
    const float* qkv_b  = (const float*)d_in[2];
    const float* relh   = (const float*)d_in[3];
    const float* relw   = (const float*)d_in[4];
    const float* proj_w = (const float*)d_in[5];
    const float* proj_b = (const float*)d_in[6];
    float* out = (float*)d_out;

    cudaFuncSetAttribute(attn_mma,
                         cudaFuncAttributeMaxDynamicSharedMemorySize, ATT_SMEM);

    // 0) one-shot bf16 hi/lo splits
    {
        const int n2x = MTOT * DIM / 2;
        split_kernel<0><<<(n2x + 255) / 256, 256>>>(x, n2x);
        const int n2q = 3 * DIM * DIM / 2;
        split_kernel<1><<<(n2q + 255) / 256, 256>>>(qkv_w, n2q);
        const int n2p = DIM * DIM / 2;
        split_kernel<2><<<(n2p + 255) / 256, 256>>>(proj_w, n2p);
    }

    // 1) QKV GEMM -> g_q (fp32), g_k hi/lo, g_v hi/lo transposed
    gemm_mma<0><<<dim3(2304 / 128, MTOT / 128), 256>>>(qkv_b, nullptr);

    // 2) tensor-core flash attention per (b, head) -> g_aoH/g_aoL
    attn_mma<<<BATCH * NH, ATHR, ATT_SMEM>>>(relh, relw);

    // 3) proj GEMM -> d_out
    gemm_mma<1><<<dim3(DIM / 128, MTOT / 128), 256>>>(proj_b, out);
}